// round 13
// baseline (speedup 1.0000x reference)
#include <cuda_runtime.h>
#include <cuda_fp16.h>
#include <cfloat>
#include <math.h>
#include <cstdint>

#define B_   8
#define N_   4096
#define M_   64
#define DIM_ 1024
#define H_   16
#define DH_  64
#define INNER_ 1024
#define KV2_  2048
#define NCH_  4

// ==================== scratch =============================================
__device__ float    g_q[B_ * M_ * INNER_];
__device__ __half   g_k16[(size_t)B_ * N_ * INNER_];
__device__ __half   g_vh16[(size_t)B_ * N_ * INNER_];
__device__ __half   g_vl16[(size_t)B_ * N_ * INNER_];
__device__ float    g_sim[(size_t)B_ * H_ * M_ * N_];
__device__ unsigned g_rmax_ord[B_ * H_ * M_];
__device__ float    g_losspart[B_ * H_];
__device__ float    g_pvpart[B_ * H_ * NCH_ * M_ * DH_];
__device__ float    g_denpart[B_ * H_ * NCH_ * M_];
__device__ float    g_losschunk[B_ * H_ * NCH_];

// fp16 split buffers
__device__ __half g_xh[(size_t)B_ * N_ * DIM_];
__device__ __half g_xl[(size_t)B_ * N_ * DIM_];
__device__ __half g_wkvh[KV2_ * DIM_];
__device__ __half g_wqh[INNER_ * DIM_];
__device__ __half g_wouth[DIM_ * INNER_];
__device__ __half g_lath[B_ * M_ * DIM_];
__device__ __half g_latl[B_ * M_ * DIM_];
__device__ __half g_ah[B_ * M_ * INNER_];
__device__ __half g_al[B_ * M_ * INNER_];
__device__ __half g_qh16[B_ * M_ * INNER_];
__device__ __half g_ql16[B_ * M_ * INNER_];

// ==================== helpers =============================================
__device__ __forceinline__ uint32_t smem_u32(const void* p) {
    uint32_t a;
    asm("{ .reg .u64 t; cvta.to.shared.u64 t, %1; cvt.u32.u64 %0, t; }" : "=r"(a) : "l"(p));
    return a;
}
__device__ __forceinline__ uint32_t lds32(uint32_t a) {
    uint32_t v;
    asm volatile("ld.shared.b32 %0, [%1];" : "=r"(v) : "r"(a));
    return v;
}
#define LDMX4(r, addr) \
    asm volatile("ldmatrix.sync.aligned.m8n8.x4.shared.b16 {%0,%1,%2,%3}, [%4];" \
        : "=r"((r)[0]), "=r"((r)[1]), "=r"((r)[2]), "=r"((r)[3]) : "r"(addr))
#define LDMX2T(r, addr) \
    asm volatile("ldmatrix.sync.aligned.m8n8.x2.trans.shared.b16 {%0,%1}, [%2];" \
        : "=r"((r)[0]), "=r"((r)[1]) : "r"(addr))
#define MMA_F16(c, a, b) \
    asm volatile("mma.sync.aligned.m16n8k16.row.col.f32.f16.f16.f32 " \
        "{%0,%1,%2,%3}, {%4,%5,%6,%7}, {%8,%9}, {%0,%1,%2,%3};" \
        : "+f"((c)[0]), "+f"((c)[1]), "+f"((c)[2]), "+f"((c)[3]) \
        : "r"((a)[0]), "r"((a)[1]), "r"((a)[2]), "r"((a)[3]), "r"((b)[0]), "r"((b)[1]))
#define CP_ASYNC16(dst, src) \
    asm volatile("cp.async.cg.shared.global [%0], [%1], 16;" :: "r"(dst), "l"(src) : "memory")
#define CP_COMMIT asm volatile("cp.async.commit_group;" ::: "memory")
#define CP_WAIT1  asm volatile("cp.async.wait_group 1;" ::: "memory")
#define CP_WAIT0  asm volatile("cp.async.wait_group 0;" ::: "memory")
#define SW128(off) ((off) ^ (((off) >> 3) & 0x70))

__device__ __forceinline__ uint2 hi_pack_h(float4 v) {
    __half2 p0(__float2half_rn(v.x), __float2half_rn(v.y));
    __half2 p1(__float2half_rn(v.z), __float2half_rn(v.w));
    uint2 r;
    r.x = *reinterpret_cast<uint32_t*>(&p0);
    r.y = *reinterpret_cast<uint32_t*>(&p1);
    return r;
}
__device__ __forceinline__ uint2 lo_pack_h(float4 v) {
    float4 l;
    l.x = v.x - __half2float(__float2half_rn(v.x));
    l.y = v.y - __half2float(__float2half_rn(v.y));
    l.z = v.z - __half2float(__float2half_rn(v.z));
    l.w = v.w - __half2float(__float2half_rn(v.w));
    return hi_pack_h(l);
}
__device__ __forceinline__ unsigned f2o(float f) {
    unsigned b = __float_as_uint(f);
    return (b & 0x80000000u) ? ~b : (b | 0x80000000u);
}
__device__ __forceinline__ float o2f(unsigned u) {
    return __uint_as_float((u & 0x80000000u) ? (u ^ 0x80000000u) : ~u);
}

// ==================== split kernels =======================================
__global__ __launch_bounds__(256) void split2_kernel(
    const float* __restrict__ src, __half* __restrict__ h, __half* __restrict__ l, int n4)
{
    int i = blockIdx.x * 256 + threadIdx.x;
    if (i >= n4) return;
    float4 v = reinterpret_cast<const float4*>(src)[i];
    reinterpret_cast<uint2*>(h)[i] = hi_pack_h(v);
    reinterpret_cast<uint2*>(l)[i] = lo_pack_h(v);
}

#define PR_WKV  524288
#define PR_WQ   (PR_WKV + 262144)
#define PR_WOUT (PR_WQ + 262144)
#define PR_LAT  (PR_WOUT + 131072)
#define PR_RM   (PR_LAT + 1024)
#define PR_END  (PR_RM + 128)
__global__ __launch_bounds__(256) void prep_kernel(
    const float* __restrict__ Wkv, const float* __restrict__ Wq,
    const float* __restrict__ Wout, const float* __restrict__ latents)
{
    int id = blockIdx.x * 256 + threadIdx.x;
    if (id < PR_WKV) {
        float4 v = reinterpret_cast<const float4*>(Wkv)[id];
        reinterpret_cast<uint2*>(g_wkvh)[id] = hi_pack_h(v);
    } else if (id < PR_WQ) {
        int i = id - PR_WKV;
        float4 v = reinterpret_cast<const float4*>(Wq)[i];
        reinterpret_cast<uint2*>(g_wqh)[i] = hi_pack_h(v);
    } else if (id < PR_WOUT) {
        int i = id - PR_WQ;
        float4 v = reinterpret_cast<const float4*>(Wout)[i];
        reinterpret_cast<uint2*>(g_wouth)[i] = hi_pack_h(v);
    } else if (id < PR_LAT) {
        int i = id - PR_WOUT;
        float4 v = reinterpret_cast<const float4*>(latents)[i];
        reinterpret_cast<uint2*>(g_lath)[i] = hi_pack_h(v);
        reinterpret_cast<uint2*>(g_latl)[i] = lo_pack_h(v);
    } else if (id < PR_RM) {
        g_rmax_ord[id - PR_LAT] = 0u;
    } else if (id < PR_END) {
        g_losspart[id - PR_RM] = 0.f;
    }
}

// ==================== fp16 GEMM: 128x256 tile, 512 thr, 3-stage ===========
// C = alpha * (Ah [+ Al]) * Bh^T.  Al null => 1-pass.
// Outputs: C fp32 (opt), Ch fp16 (opt); Chl (opt) => Ch/Chl hi/lo split.
// Warp grid 2x8, warp tile 64x32 (identical per-warp pattern to R9 kernel).
#define A_TILE3    16384        // 128 rows * 128B
#define B_OFF3     32768        // A hi + A lo
#define STAGE3     65536        // A hi 16K + A lo 16K + B 32K
#define GSMEM3     196608       // 3 stages

__global__ __launch_bounds__(512, 1) void gemm16_kernel(
    const __half* __restrict__ Ah, const __half* __restrict__ Al,
    const __half* __restrict__ Bh, float* __restrict__ C,
    __half* __restrict__ Ch, __half* __restrict__ Chl,
    int Ng, int Kg, float alpha)
{
    extern __shared__ char sm[];
    const uint32_t smb = smem_u32(sm);
    const int tid  = threadIdx.x;
    const int lane = tid & 31;
    const int wid  = tid >> 5;       // 0..15
    const int wm   = wid >> 3;       // 0..1  -> 64 rows
    const int wn   = wid & 7;        // 0..7  -> 32 cols
    const int row0 = blockIdx.y * 128;
    const int col0 = blockIdx.x * 256;
    const bool two_pass = (Al != nullptr);

    float acc[4][4][4];
#pragma unroll
    for (int mt = 0; mt < 4; mt++)
#pragma unroll
        for (int nt = 0; nt < 4; nt++)
#pragma unroll
            for (int e = 0; e < 4; e++) acc[mt][nt][e] = 0.f;

#define LOAD(i) do { \
    const int s_ = (i) % 3; \
    const uint32_t sb_ = smb + s_ * STAGE3; \
    const int k0_ = (i) * 64; \
    _Pragma("unroll") \
    for (int c_ = 0; c_ < 2; c_++) { \
        int id_ = tid + c_ * 512;           /* 0..1023 -> A tiles */ \
        int r_ = id_ >> 3, c16_ = id_ & 7; \
        uint32_t doff_ = SW128((uint32_t)(r_ * 128 + c16_ * 16)); \
        CP_ASYNC16(sb_ + doff_,              (const void*)&Ah[(size_t)(row0 + r_) * Kg + k0_ + c16_ * 8]); \
        if (two_pass) \
            CP_ASYNC16(sb_ + A_TILE3 + doff_, (const void*)&Al[(size_t)(row0 + r_) * Kg + k0_ + c16_ * 8]); \
    } \
    _Pragma("unroll") \
    for (int c_ = 0; c_ < 4; c_++) { \
        int id_ = tid + c_ * 512;           /* 0..2047 -> B tile (256 rows) */ \
        int r_ = id_ >> 3, c16_ = id_ & 7; \
        uint32_t doff_ = SW128((uint32_t)(r_ * 128 + c16_ * 16)); \
        CP_ASYNC16(sb_ + B_OFF3 + doff_, (const void*)&Bh[(size_t)(col0 + r_) * Kg + k0_ + c16_ * 8]); \
    } } while (0)

#define COMPUTE(s) do { \
    const uint32_t sb_ = smb + (s) * STAGE3; \
    _Pragma("unroll") \
    for (int ks = 0; ks < 4; ks++) { \
        uint32_t ah[4][4], al[4][4], bh[4][2]; \
        _Pragma("unroll") \
        for (int mt = 0; mt < 4; mt++) { \
            uint32_t r_ = wm * 64 + mt * 16 + (lane & 15); \
            uint32_t off_ = SW128(r_ * 128 + ks * 32 + (lane >> 4) * 16); \
            LDMX4(ah[mt], sb_ + off_); \
            if (two_pass) LDMX4(al[mt], sb_ + A_TILE3 + off_); \
        } \
        _Pragma("unroll") \
        for (int nt = 0; nt < 4; nt++) { \
            uint32_t n_ = wn * 32 + nt * 8 + (lane >> 2); \
            bh[nt][0] = lds32(sb_ + B_OFF3 + SW128(n_ * 128 + ks * 32 + (lane & 3) * 4)); \
            bh[nt][1] = lds32(sb_ + B_OFF3 + SW128(n_ * 128 + ks * 32 + 16 + (lane & 3) * 4)); \
        } \
        _Pragma("unroll") \
        for (int mt = 0; mt < 4; mt++) \
        _Pragma("unroll") \
        for (int nt = 0; nt < 4; nt++) { \
            MMA_F16(acc[mt][nt], ah[mt], bh[nt]); \
            if (two_pass) MMA_F16(acc[mt][nt], al[mt], bh[nt]); \
        } \
    } } while (0)

    const int nk = Kg >> 6;
    LOAD(0); CP_COMMIT;
    LOAD(1); CP_COMMIT;
    for (int i = 0; i < nk; i++) {
        if (i + 1 < nk) { CP_WAIT1; } else { CP_WAIT0; }
        __syncthreads();
        if (i + 2 < nk) { LOAD(i + 2); CP_COMMIT; }
        COMPUTE(i % 3);
    }

#pragma unroll
    for (int mt = 0; mt < 4; mt++) {
        int r = row0 + wm * 64 + mt * 16 + (lane >> 2);
#pragma unroll
        for (int nt = 0; nt < 4; nt++) {
            int c = col0 + wn * 32 + nt * 8 + (lane & 3) * 2;
            float2 v0 = make_float2(alpha * acc[mt][nt][0], alpha * acc[mt][nt][1]);
            float2 v1 = make_float2(alpha * acc[mt][nt][2], alpha * acc[mt][nt][3]);
            if (C) {
                *reinterpret_cast<float2*>(&C[(size_t)r * Ng + c]) = v0;
                *reinterpret_cast<float2*>(&C[(size_t)(r + 8) * Ng + c]) = v1;
            }
            if (Ch) {
                __half h00 = __float2half_rn(v0.x), h01 = __float2half_rn(v0.y);
                __half h10 = __float2half_rn(v1.x), h11 = __float2half_rn(v1.y);
                *reinterpret_cast<__half2*>(&Ch[(size_t)r * Ng + c]) = __half2(h00, h01);
                *reinterpret_cast<__half2*>(&Ch[(size_t)(r + 8) * Ng + c]) = __half2(h10, h11);
                if (Chl) {
                    __half2 l0(__float2half_rn(v0.x - __half2float(h00)),
                               __float2half_rn(v0.y - __half2float(h01)));
                    __half2 l1(__float2half_rn(v1.x - __half2float(h10)),
                               __float2half_rn(v1.y - __half2float(h11)));
                    *reinterpret_cast<__half2*>(&Chl[(size_t)r * Ng + c]) = l0;
                    *reinterpret_cast<__half2*>(&Chl[(size_t)(r + 8) * Ng + c]) = l1;
                }
            }
        }
    }
#undef LOAD
#undef COMPUTE
}

// ==================== sim via mma.sync + mask + rowmax ====================
__global__ __launch_bounds__(256) void sim_mma_kernel(const int* __restrict__ mask)
{
    const int bh = blockIdx.y;
    const int b  = bh >> 4;
    const int h  = bh & 15;
    const int n0 = blockIdx.x * 128;
    const int tid = threadIdx.x;
    const int lane = tid & 31;
    const int wid  = tid >> 5;
    const int wm   = wid >> 2;
    const int wn   = wid & 3;

    __shared__ __half sqh[64 * 64];
    __shared__ __half sql[64 * 64];
    __shared__ __half skh[128 * 64];
    __shared__ int    msk[128];
    __shared__ float  redm[64][5];

    const uint32_t bqh = smem_u32(sqh);
    const uint32_t bql = smem_u32(sql);
    const uint32_t bkh = smem_u32(skh);

#pragma unroll
    for (int c = 0; c < 2; c++) {
        int id = tid + c * 256;
        int r = id >> 3, c16 = id & 7;
        uint32_t off = SW128((uint32_t)(r * 128 + c16 * 16));
        CP_ASYNC16(bqh + off, (const void*)&g_qh16[(size_t)(b * M_ + r) * INNER_ + h * DH_ + c16 * 8]);
        CP_ASYNC16(bql + off, (const void*)&g_ql16[(size_t)(b * M_ + r) * INNER_ + h * DH_ + c16 * 8]);
    }
#pragma unroll
    for (int c = 0; c < 4; c++) {
        int id = tid + c * 256;
        int r = id >> 3, c16 = id & 7;
        uint32_t off = SW128((uint32_t)(r * 128 + c16 * 16));
        CP_ASYNC16(bkh + off, (const void*)&g_k16[((size_t)b * N_ + n0 + r) * INNER_ + h * DH_ + c16 * 8]);
    }
    CP_COMMIT;
    if (tid < 128) msk[tid] = mask[b * N_ + n0 + tid];
    CP_WAIT0;
    __syncthreads();

    float acc[2][4][4];
#pragma unroll
    for (int mt = 0; mt < 2; mt++)
#pragma unroll
        for (int nt = 0; nt < 4; nt++)
#pragma unroll
            for (int e = 0; e < 4; e++) acc[mt][nt][e] = 0.f;

#pragma unroll
    for (int ks = 0; ks < 4; ks++) {
        uint32_t ah[2][4], al[2][4], bf[4][2];
#pragma unroll
        for (int mt = 0; mt < 2; mt++) {
            uint32_t r_ = wm * 32 + mt * 16 + (lane & 15);
            uint32_t off = SW128(r_ * 128 + ks * 32 + (lane >> 4) * 16);
            LDMX4(ah[mt], bqh + off);
            LDMX4(al[mt], bql + off);
        }
#pragma unroll
        for (int nt = 0; nt < 4; nt++) {
            uint32_t n_ = wn * 32 + nt * 8 + (lane >> 2);
            bf[nt][0] = lds32(bkh + SW128(n_ * 128 + ks * 32 + (lane & 3) * 4));
            bf[nt][1] = lds32(bkh + SW128(n_ * 128 + ks * 32 + 16 + (lane & 3) * 4));
        }
#pragma unroll
        for (int mt = 0; mt < 2; mt++)
#pragma unroll
            for (int nt = 0; nt < 4; nt++) {
                MMA_F16(acc[mt][nt], ah[mt], bf[nt]);
                MMA_F16(acc[mt][nt], al[mt], bf[nt]);
            }
    }

#pragma unroll
    for (int mt = 0; mt < 2; mt++) {
        int r = wm * 32 + mt * 16 + (lane >> 2);
        float m0 = -FLT_MAX, m1 = -FLT_MAX;
#pragma unroll
        for (int nt = 0; nt < 4; nt++) {
            int c = wn * 32 + nt * 8 + (lane & 3) * 2;
            float v0 = msk[c]     ? -FLT_MAX : acc[mt][nt][0];
            float v1 = msk[c + 1] ? -FLT_MAX : acc[mt][nt][1];
            float v2 = msk[c]     ? -FLT_MAX : acc[mt][nt][2];
            float v3 = msk[c + 1] ? -FLT_MAX : acc[mt][nt][3];
            *reinterpret_cast<float2*>(&g_sim[((size_t)bh * M_ + r) * N_ + n0 + c]) = make_float2(v0, v1);
            *reinterpret_cast<float2*>(&g_sim[((size_t)bh * M_ + r + 8) * N_ + n0 + c]) = make_float2(v2, v3);
            m0 = fmaxf(m0, fmaxf(v0, v1));
            m1 = fmaxf(m1, fmaxf(v2, v3));
        }
#pragma unroll
        for (int s = 1; s < 4; s <<= 1) {
            m0 = fmaxf(m0, __shfl_xor_sync(0xffffffffu, m0, s));
            m1 = fmaxf(m1, __shfl_xor_sync(0xffffffffu, m1, s));
        }
        if ((lane & 3) == 0) {
            redm[r][wn]     = m0;
            redm[r + 8][wn] = m1;
        }
    }
    __syncthreads();
    if (tid < 64) {
        float m = fmaxf(fmaxf(redm[tid][0], redm[tid][1]), fmaxf(redm[tid][2], redm[tid][3]));
        atomicMax(&g_rmax_ord[bh * M_ + tid], f2o(m));
    }
}

// ==================== pv via mma ==========================================
#define PVROW 72
__global__ __launch_bounds__(256) void pv_mma_kernel(const int* __restrict__ mask)
{
    const int ch = blockIdx.x;
    const int bh = blockIdx.y;
    const int b  = bh >> 4;
    const int h  = bh & 15;
    const int tid = threadIdx.x;
    const int lane = tid & 31;
    const int wid  = tid >> 5;
    const int wm   = wid >> 2;
    const int wn   = wid & 3;

    __shared__ __half ph[64 * PVROW];
    __shared__ __half pl[64 * PVROW];
    __shared__ __half vh[64 * PVROW];
    __shared__ __half vl[64 * PVROW];
    __shared__ float  rs[64];
    __shared__ float  colred[2][4][64];
    __shared__ float  lred[64];

    const uint32_t bph = smem_u32(ph);
    const uint32_t bpl = smem_u32(pl);
    const uint32_t bvh = smem_u32(vh);
    const uint32_t bvl = smem_u32(vl);

    if (tid < 64) rs[tid] = o2f(g_rmax_ord[bh * M_ + tid]);
    __syncthreads();

    const int cq = tid >> 6;
    const int ccol = tid & 63;

    float acc[2][2][4];
#pragma unroll
    for (int mt = 0; mt < 2; mt++)
#pragma unroll
        for (int nt = 0; nt < 2; nt++)
#pragma unroll
            for (int e = 0; e < 4; e++) acc[mt][nt][e] = 0.f;
    float lossloc = 0.f, denloc = 0.f;

    const int jt0 = ch * (64 / NCH_);
    for (int jt = jt0; jt < jt0 + 64 / NCH_; jt++) {
        const int j0 = jt * 64;

#pragma unroll
        for (int c = 0; c < 2; c++) {
            int id = tid + c * 256;
            int r = id >> 3, c16 = id & 7;
            uint32_t doff = (uint32_t)(r * (PVROW * 2) + c16 * 16);
            size_t gsrc = ((size_t)b * N_ + j0 + r) * INNER_ + h * DH_ + c16 * 8;
            CP_ASYNC16(bvh + doff, (const void*)&g_vh16[gsrc]);
            CP_ASYNC16(bvl + doff, (const void*)&g_vl16[gsrc]);
        }
        CP_COMMIT;

        float st = 0.f, st2 = 0.f;
#pragma unroll 4
        for (int k = 0; k < 16; k++) {
            int r = cq + 4 * k;
            float sv = g_sim[((size_t)bh * M_ + r) * N_ + j0 + ccol];
            float t = sv - rs[r];
            float e = __expf(t);
            __half hp = __float2half_rn(e);
            __half lp = __float2half_rn(e - __half2float(hp));
            ph[r * PVROW + ccol] = hp;
            pl[r * PVROW + ccol] = lp;
            st += t; st2 += t * t;
        }
        colred[0][cq][ccol] = st;
        colred[1][cq][ccol] = st2;
        CP_WAIT0;
        __syncthreads();

        if (tid < 64) {
            if (mask[b * N_ + j0 + tid] == 0) {
                float s  = colred[0][0][tid] + colred[0][1][tid] + colred[0][2][tid] + colred[0][3][tid];
                float ss = colred[1][0][tid] + colred[1][1][tid] + colred[1][2][tid] + colred[1][3][tid];
                float var = (ss - s * s * (1.0f / 64.f)) * (1.0f / 63.f);
                float sd  = sqrtf(var + 1e-4f);
                lossloc += fmaxf(1.0f - sd, 0.0f);
            }
            float sde = 0.f;
            const __half2* rh = reinterpret_cast<const __half2*>(&ph[tid * PVROW]);
            const __half2* rl = reinterpret_cast<const __half2*>(&pl[tid * PVROW]);
#pragma unroll 8
            for (int j2 = 0; j2 < 32; j2++) {
                float2 a = __half22float2(rh[j2]);
                float2 c2 = __half22float2(rl[j2]);
                sde += a.x + a.y + c2.x + c2.y;
            }
            denloc += sde;
        }

#pragma unroll
        for (int ks = 0; ks < 4; ks++) {
            uint32_t aph[2][4], apl[2][4], bh2[2][2], bl2[2][2];
#pragma unroll
            for (int mt = 0; mt < 2; mt++) {
                uint32_t r_ = wm * 32 + mt * 16 + (lane & 15);
                uint32_t off = r_ * (PVROW * 2) + ks * 32 + (lane >> 4) * 16;
                LDMX4(aph[mt], bph + off);
                LDMX4(apl[mt], bpl + off);
            }
#pragma unroll
            for (int nt = 0; nt < 2; nt++) {
                uint32_t jr = (uint32_t)(ks * 16 + (lane & 15));
                uint32_t off = jr * (PVROW * 2) + (wn * 16 + nt * 8) * 2;
                LDMX2T(bh2[nt], bvh + off);
                LDMX2T(bl2[nt], bvl + off);
            }
#pragma unroll
            for (int mt = 0; mt < 2; mt++)
#pragma unroll
                for (int nt = 0; nt < 2; nt++) {
                    MMA_F16(acc[mt][nt], aph[mt], bh2[nt]);
                    MMA_F16(acc[mt][nt], aph[mt], bl2[nt]);
                    MMA_F16(acc[mt][nt], apl[mt], bh2[nt]);
                }
        }
        __syncthreads();
    }

    float* pvb = &g_pvpart[((size_t)bh * NCH_ + ch) * M_ * DH_];
#pragma unroll
    for (int mt = 0; mt < 2; mt++) {
        int i = wm * 32 + mt * 16 + (lane >> 2);
#pragma unroll
        for (int nt = 0; nt < 2; nt++) {
            int d = wn * 16 + nt * 8 + (lane & 3) * 2;
            *reinterpret_cast<float2*>(&pvb[i * DH_ + d]) = make_float2(acc[mt][nt][0], acc[mt][nt][1]);
            *reinterpret_cast<float2*>(&pvb[(i + 8) * DH_ + d]) = make_float2(acc[mt][nt][2], acc[mt][nt][3]);
        }
    }
    if (tid < 64) g_denpart[(bh * NCH_ + ch) * M_ + tid] = denloc;

    if (tid < 64) lred[tid] = lossloc;
    __syncthreads();
    if (tid < 32) lred[tid] += lred[tid + 32];
    __syncthreads();
    if (tid == 0) {
        float s = 0.f;
#pragma unroll
        for (int t = 0; t < 32; t++) s += lred[t];
        g_losschunk[bh * NCH_ + ch] = s;
    }
}

// ==================== pv combine -> attn fp16 hi/lo =======================
__global__ __launch_bounds__(256) void pv_combine_kernel()
{
    const int bh = blockIdx.x;
    const int b  = bh >> 4;
    const int h  = bh & 15;
    const int tid = threadIdx.x;

    __shared__ float dinv[64];
    if (tid < 64) {
        float d = 0.f;
#pragma unroll
        for (int c = 0; c < NCH_; c++) d += g_denpart[(bh * NCH_ + c) * M_ + tid];
        dinv[tid] = 1.0f / d;
    }
    if (tid == 64) {
        float s = 0.f;
#pragma unroll
        for (int c = 0; c < NCH_; c++) s += g_losschunk[bh * NCH_ + c];
        g_losspart[bh] = s;
    }
    __syncthreads();

    const float* pvb = &g_pvpart[(size_t)bh * NCH_ * M_ * DH_];
    for (int idx = tid; idx < M_ * DH_; idx += 256) {
        int i = idx >> 6, d = idx & 63;
        float s = 0.f;
#pragma unroll
        for (int c = 0; c < NCH_; c++) s += pvb[c * M_ * DH_ + idx];
        float val = s * dinv[i];
        __half hp = __float2half_rn(val);
        __half lp = __float2half_rn(val - __half2float(hp));
        size_t gi = ((size_t)b * M_ + i) * INNER_ + h * DH_ + d;
        g_ah[gi] = hp;
        g_al[gi] = lp;
    }
}

__global__ __launch_bounds__(128) void loss_final_kernel(float* __restrict__ out, int idx)
{
    __shared__ float red[128];
    red[threadIdx.x] = g_losspart[threadIdx.x];
    __syncthreads();
    for (int t = 64; t > 0; t >>= 1) {
        if (threadIdx.x < t) red[threadIdx.x] += red[threadIdx.x + t];
        __syncthreads();
    }
    if (threadIdx.x == 0) out[idx] = red[0] * (1.0f / (float)(B_ * H_ * N_));
}

// ==================== launch ==============================================
extern "C" void kernel_launch(void* const* d_in, const int* in_sizes, int n_in,
                              void* d_out, int out_size)
{
    const float* x       = (const float*)d_in[0];
    const float* latents = (const float*)d_in[1];
    const int*   mask    = (const int*)d_in[2];
    const float* Wq      = (const float*)d_in[3];
    const float* Wkv     = (const float*)d_in[4];
    const float* Wout    = (const float*)d_in[5];
    float*       out     = (float*)d_out;

    cudaFuncSetAttribute(gemm16_kernel, cudaFuncAttributeMaxDynamicSharedMemorySize, GSMEM3);

    void *pxh, *pxl, *pkvh, *pqh, *poh, *plh, *pll, *pah, *pal;
    void *pq, *pvh, *pvl, *pk16, *pqh16, *pql16;
    cudaGetSymbolAddress(&pxh, g_xh);   cudaGetSymbolAddress(&pxl, g_xl);
    cudaGetSymbolAddress(&pkvh, g_wkvh);
    cudaGetSymbolAddress(&pqh, g_wqh);  cudaGetSymbolAddress(&poh, g_wouth);
    cudaGetSymbolAddress(&plh, g_lath); cudaGetSymbolAddress(&pll, g_latl);
    cudaGetSymbolAddress(&pah, g_ah);   cudaGetSymbolAddress(&pal, g_al);
    cudaGetSymbolAddress(&pq, g_q);
    cudaGetSymbolAddress(&pvh, g_vh16); cudaGetSymbolAddress(&pvl, g_vl16);
    cudaGetSymbolAddress(&pk16, g_k16);
    cudaGetSymbolAddress(&pqh16, g_qh16);
    cudaGetSymbolAddress(&pql16, g_ql16);

    const __half* wk_h = (const __half*)pkvh;
    const __half* wv_h = (const __half*)pkvh + (size_t)INNER_ * DIM_;

    // L1: split x -> fp16 hi/lo
    split2_kernel<<<(B_ * N_ * DIM_ / 4 + 255) / 256, 256>>>(
        x, (__half*)pxh, (__half*)pxl, B_ * N_ * DIM_ / 4);

    // L2: split weights + latents, init rmax/loss
    prep_kernel<<<(PR_END + 255) / 256, 256>>>(Wkv, Wq, Wout, latents);

    // L3: q = latents @ Wq^T * scale  (2-pass fp32)
    gemm16_kernel<<<dim3(INNER_ / 256, (B_ * M_) / 128), 512, GSMEM3>>>(
        (const __half*)plh, (const __half*)pll, (const __half*)pqh,
        (float*)pq, nullptr, nullptr, INNER_, DIM_, 0.125f);

    // L4: k16 = x_h @ Wk^T  (1-pass, fp16)   (profiled launch)
    gemm16_kernel<<<dim3(INNER_ / 256, (B_ * N_) / 128), 512, GSMEM3>>>(
        (const __half*)pxh, nullptr, wk_h,
        nullptr, (__half*)pk16, nullptr, INNER_, DIM_, 1.0f);

    // L5: v = (x_hi + x_lo) @ Wv^T  (2-pass, fp16 hi/lo output)
    gemm16_kernel<<<dim3(INNER_ / 256, (B_ * N_) / 128), 512, GSMEM3>>>(
        (const __half*)pxh, (const __half*)pxl, wv_h,
        nullptr, (__half*)pvh, (__half*)pvl, INNER_, DIM_, 1.0f);

    // L6: split q -> fp16 hi/lo for sim
    split2_kernel<<<(B_ * M_ * INNER_ / 4 + 255) / 256, 256>>>(
        (const float*)pq, (__half*)pqh16, (__half*)pql16, B_ * M_ * INNER_ / 4);

    // L7: sim via tensor cores
    sim_mma_kernel<<<dim3(N_ / 128, B_ * H_), 256>>>(mask);

    // L8: pv via tensor cores
    pv_mma_kernel<<<dim3(NCH_, B_ * H_), 256>>>(mask);

    // L9: combine -> attn fp16 hi/lo
    pv_combine_kernel<<<B_ * H_, 256>>>();

    // L10: loss finalize
    loss_final_kernel<<<1, 128>>>(out, out_size - 1);

    // L11: out = attn_out @ Wout^T  (2-pass fp32)
    gemm16_kernel<<<dim3(DIM_ / 256, (B_ * M_) / 128), 512, GSMEM3>>>(
        (const __half*)pah, (const __half*)pal, (const __half*)poh,
        out, nullptr, nullptr, DIM_, INNER_, 1.0f);
}

// round 14
// speedup vs baseline: 1.0230x; 1.0230x over previous
#include <cuda_runtime.h>
#include <cuda_fp16.h>
#include <cfloat>
#include <math.h>
#include <cstdint>

#define B_   8
#define N_   4096
#define M_   64
#define DIM_ 1024
#define H_   16
#define DH_  64
#define INNER_ 1024
#define KV2_  2048
#define NCH_  4

// ==================== scratch =============================================
__device__ float    g_q[B_ * M_ * INNER_];
__device__ __half   g_k16[(size_t)B_ * N_ * INNER_];
__device__ __half   g_vh16[(size_t)B_ * N_ * INNER_];
__device__ __half   g_vl16[(size_t)B_ * N_ * INNER_];
__device__ float    g_sim[(size_t)B_ * H_ * M_ * N_];
__device__ unsigned g_rmax_ord[B_ * H_ * M_];
__device__ float    g_losspart[B_ * H_];
__device__ float    g_pvpart[B_ * H_ * NCH_ * M_ * DH_];
__device__ float    g_denpart[B_ * H_ * NCH_ * M_];
__device__ float    g_losschunk[B_ * H_ * NCH_];

// fp16 split buffers
__device__ __half g_xh[(size_t)B_ * N_ * DIM_];
__device__ __half g_wkvh[KV2_ * DIM_];
__device__ __half g_wqh[INNER_ * DIM_];
__device__ __half g_wouth[DIM_ * INNER_];
__device__ __half g_lath[B_ * M_ * DIM_];
__device__ __half g_latl[B_ * M_ * DIM_];
__device__ __half g_ah[B_ * M_ * INNER_];
__device__ __half g_al[B_ * M_ * INNER_];
__device__ __half g_qh16[B_ * M_ * INNER_];
__device__ __half g_ql16[B_ * M_ * INNER_];

// ==================== helpers =============================================
__device__ __forceinline__ uint32_t smem_u32(const void* p) {
    uint32_t a;
    asm("{ .reg .u64 t; cvta.to.shared.u64 t, %1; cvt.u32.u64 %0, t; }" : "=r"(a) : "l"(p));
    return a;
}
__device__ __forceinline__ uint32_t lds32(uint32_t a) {
    uint32_t v;
    asm volatile("ld.shared.b32 %0, [%1];" : "=r"(v) : "r"(a));
    return v;
}
#define LDMX4(r, addr) \
    asm volatile("ldmatrix.sync.aligned.m8n8.x4.shared.b16 {%0,%1,%2,%3}, [%4];" \
        : "=r"((r)[0]), "=r"((r)[1]), "=r"((r)[2]), "=r"((r)[3]) : "r"(addr))
#define LDMX2T(r, addr) \
    asm volatile("ldmatrix.sync.aligned.m8n8.x2.trans.shared.b16 {%0,%1}, [%2];" \
        : "=r"((r)[0]), "=r"((r)[1]) : "r"(addr))
#define MMA_F16(c, a, b) \
    asm volatile("mma.sync.aligned.m16n8k16.row.col.f32.f16.f16.f32 " \
        "{%0,%1,%2,%3}, {%4,%5,%6,%7}, {%8,%9}, {%0,%1,%2,%3};" \
        : "+f"((c)[0]), "+f"((c)[1]), "+f"((c)[2]), "+f"((c)[3]) \
        : "r"((a)[0]), "r"((a)[1]), "r"((a)[2]), "r"((a)[3]), "r"((b)[0]), "r"((b)[1]))
#define CP_ASYNC16(dst, src) \
    asm volatile("cp.async.cg.shared.global [%0], [%1], 16;" :: "r"(dst), "l"(src) : "memory")
#define CP_COMMIT asm volatile("cp.async.commit_group;" ::: "memory")
#define CP_WAIT1  asm volatile("cp.async.wait_group 1;" ::: "memory")
#define CP_WAIT0  asm volatile("cp.async.wait_group 0;" ::: "memory")
#define SW128(off) ((off) ^ (((off) >> 3) & 0x70))

__device__ __forceinline__ uint2 hi_pack_h(float4 v) {
    __half2 p0(__float2half_rn(v.x), __float2half_rn(v.y));
    __half2 p1(__float2half_rn(v.z), __float2half_rn(v.w));
    uint2 r;
    r.x = *reinterpret_cast<uint32_t*>(&p0);
    r.y = *reinterpret_cast<uint32_t*>(&p1);
    return r;
}
__device__ __forceinline__ uint2 lo_pack_h(float4 v) {
    float4 l;
    l.x = v.x - __half2float(__float2half_rn(v.x));
    l.y = v.y - __half2float(__float2half_rn(v.y));
    l.z = v.z - __half2float(__float2half_rn(v.z));
    l.w = v.w - __half2float(__float2half_rn(v.w));
    return hi_pack_h(l);
}
__device__ __forceinline__ unsigned f2o(float f) {
    unsigned b = __float_as_uint(f);
    return (b & 0x80000000u) ? ~b : (b | 0x80000000u);
}
__device__ __forceinline__ float o2f(unsigned u) {
    return __uint_as_float((u & 0x80000000u) ? (u ^ 0x80000000u) : ~u);
}

// ==================== split kernels =======================================
__global__ __launch_bounds__(256) void split2_kernel(
    const float* __restrict__ src, __half* __restrict__ h, __half* __restrict__ l, int n4)
{
    int i = blockIdx.x * 256 + threadIdx.x;
    if (i >= n4) return;
    float4 v = reinterpret_cast<const float4*>(src)[i];
    reinterpret_cast<uint2*>(h)[i] = hi_pack_h(v);
    if (l) reinterpret_cast<uint2*>(l)[i] = lo_pack_h(v);
}

#define PR_WKV  524288
#define PR_WQ   (PR_WKV + 262144)
#define PR_WOUT (PR_WQ + 262144)
#define PR_LAT  (PR_WOUT + 131072)
#define PR_RM   (PR_LAT + 1024)
#define PR_END  (PR_RM + 128)
__global__ __launch_bounds__(256) void prep_kernel(
    const float* __restrict__ Wkv, const float* __restrict__ Wq,
    const float* __restrict__ Wout, const float* __restrict__ latents)
{
    int id = blockIdx.x * 256 + threadIdx.x;
    if (id < PR_WKV) {
        float4 v = reinterpret_cast<const float4*>(Wkv)[id];
        reinterpret_cast<uint2*>(g_wkvh)[id] = hi_pack_h(v);
    } else if (id < PR_WQ) {
        int i = id - PR_WKV;
        float4 v = reinterpret_cast<const float4*>(Wq)[i];
        reinterpret_cast<uint2*>(g_wqh)[i] = hi_pack_h(v);
    } else if (id < PR_WOUT) {
        int i = id - PR_WQ;
        float4 v = reinterpret_cast<const float4*>(Wout)[i];
        reinterpret_cast<uint2*>(g_wouth)[i] = hi_pack_h(v);
    } else if (id < PR_LAT) {
        int i = id - PR_WOUT;
        float4 v = reinterpret_cast<const float4*>(latents)[i];
        reinterpret_cast<uint2*>(g_lath)[i] = hi_pack_h(v);
        reinterpret_cast<uint2*>(g_latl)[i] = lo_pack_h(v);
    } else if (id < PR_RM) {
        g_rmax_ord[id - PR_LAT] = 0u;
    } else if (id < PR_END) {
        g_losspart[id - PR_RM] = 0.f;
    }
}

// ==================== fp16 GEMM: 128x256 tile, 512 thr, 3-stage ===========
#define A_TILE3    16384
#define B_OFF3     32768
#define STAGE3     65536
#define GSMEM3     196608

__global__ __launch_bounds__(512, 1) void gemm16_kernel(
    const __half* __restrict__ Ah, const __half* __restrict__ Al,
    const __half* __restrict__ Bh, float* __restrict__ C,
    __half* __restrict__ Ch, __half* __restrict__ Chl,
    int Ng, int Kg, float alpha)
{
    extern __shared__ char sm[];
    const uint32_t smb = smem_u32(sm);
    const int tid  = threadIdx.x;
    const int lane = tid & 31;
    const int wid  = tid >> 5;
    const int wm   = wid >> 3;
    const int wn   = wid & 7;
    const int row0 = blockIdx.y * 128;
    const int col0 = blockIdx.x * 256;
    const bool two_pass = (Al != nullptr);

    float acc[4][4][4];
#pragma unroll
    for (int mt = 0; mt < 4; mt++)
#pragma unroll
        for (int nt = 0; nt < 4; nt++)
#pragma unroll
            for (int e = 0; e < 4; e++) acc[mt][nt][e] = 0.f;

#define LOAD(i) do { \
    const int s_ = (i) % 3; \
    const uint32_t sb_ = smb + s_ * STAGE3; \
    const int k0_ = (i) * 64; \
    _Pragma("unroll") \
    for (int c_ = 0; c_ < 2; c_++) { \
        int id_ = tid + c_ * 512; \
        int r_ = id_ >> 3, c16_ = id_ & 7; \
        uint32_t doff_ = SW128((uint32_t)(r_ * 128 + c16_ * 16)); \
        CP_ASYNC16(sb_ + doff_,              (const void*)&Ah[(size_t)(row0 + r_) * Kg + k0_ + c16_ * 8]); \
        if (two_pass) \
            CP_ASYNC16(sb_ + A_TILE3 + doff_, (const void*)&Al[(size_t)(row0 + r_) * Kg + k0_ + c16_ * 8]); \
    } \
    _Pragma("unroll") \
    for (int c_ = 0; c_ < 4; c_++) { \
        int id_ = tid + c_ * 512; \
        int r_ = id_ >> 3, c16_ = id_ & 7; \
        uint32_t doff_ = SW128((uint32_t)(r_ * 128 + c16_ * 16)); \
        CP_ASYNC16(sb_ + B_OFF3 + doff_, (const void*)&Bh[(size_t)(col0 + r_) * Kg + k0_ + c16_ * 8]); \
    } } while (0)

#define COMPUTE(s) do { \
    const uint32_t sb_ = smb + (s) * STAGE3; \
    _Pragma("unroll") \
    for (int ks = 0; ks < 4; ks++) { \
        uint32_t ah[4][4], al[4][4], bh[4][2]; \
        _Pragma("unroll") \
        for (int mt = 0; mt < 4; mt++) { \
            uint32_t r_ = wm * 64 + mt * 16 + (lane & 15); \
            uint32_t off_ = SW128(r_ * 128 + ks * 32 + (lane >> 4) * 16); \
            LDMX4(ah[mt], sb_ + off_); \
            if (two_pass) LDMX4(al[mt], sb_ + A_TILE3 + off_); \
        } \
        _Pragma("unroll") \
        for (int nt = 0; nt < 4; nt++) { \
            uint32_t n_ = wn * 32 + nt * 8 + (lane >> 2); \
            bh[nt][0] = lds32(sb_ + B_OFF3 + SW128(n_ * 128 + ks * 32 + (lane & 3) * 4)); \
            bh[nt][1] = lds32(sb_ + B_OFF3 + SW128(n_ * 128 + ks * 32 + 16 + (lane & 3) * 4)); \
        } \
        _Pragma("unroll") \
        for (int mt = 0; mt < 4; mt++) \
        _Pragma("unroll") \
        for (int nt = 0; nt < 4; nt++) { \
            MMA_F16(acc[mt][nt], ah[mt], bh[nt]); \
            if (two_pass) MMA_F16(acc[mt][nt], al[mt], bh[nt]); \
        } \
    } } while (0)

    const int nk = Kg >> 6;
    LOAD(0); CP_COMMIT;
    LOAD(1); CP_COMMIT;
    for (int i = 0; i < nk; i++) {
        if (i + 1 < nk) { CP_WAIT1; } else { CP_WAIT0; }
        __syncthreads();
        if (i + 2 < nk) { LOAD(i + 2); CP_COMMIT; }
        COMPUTE(i % 3);
    }

#pragma unroll
    for (int mt = 0; mt < 4; mt++) {
        int r = row0 + wm * 64 + mt * 16 + (lane >> 2);
#pragma unroll
        for (int nt = 0; nt < 4; nt++) {
            int c = col0 + wn * 32 + nt * 8 + (lane & 3) * 2;
            float2 v0 = make_float2(alpha * acc[mt][nt][0], alpha * acc[mt][nt][1]);
            float2 v1 = make_float2(alpha * acc[mt][nt][2], alpha * acc[mt][nt][3]);
            if (C) {
                *reinterpret_cast<float2*>(&C[(size_t)r * Ng + c]) = v0;
                *reinterpret_cast<float2*>(&C[(size_t)(r + 8) * Ng + c]) = v1;
            }
            if (Ch) {
                __half h00 = __float2half_rn(v0.x), h01 = __float2half_rn(v0.y);
                __half h10 = __float2half_rn(v1.x), h11 = __float2half_rn(v1.y);
                *reinterpret_cast<__half2*>(&Ch[(size_t)r * Ng + c]) = __half2(h00, h01);
                *reinterpret_cast<__half2*>(&Ch[(size_t)(r + 8) * Ng + c]) = __half2(h10, h11);
                if (Chl) {
                    __half2 l0(__float2half_rn(v0.x - __half2float(h00)),
                               __float2half_rn(v0.y - __half2float(h01)));
                    __half2 l1(__float2half_rn(v1.x - __half2float(h10)),
                               __float2half_rn(v1.y - __half2float(h11)));
                    *reinterpret_cast<__half2*>(&Chl[(size_t)r * Ng + c]) = l0;
                    *reinterpret_cast<__half2*>(&Chl[(size_t)(r + 8) * Ng + c]) = l1;
                }
            }
        }
    }
#undef LOAD
#undef COMPUTE
}

// ==================== sim via mma.sync + mask + rowmax ====================
__global__ __launch_bounds__(256) void sim_mma_kernel(const int* __restrict__ mask)
{
    const int bh = blockIdx.y;
    const int b  = bh >> 4;
    const int h  = bh & 15;
    const int n0 = blockIdx.x * 128;
    const int tid = threadIdx.x;
    const int lane = tid & 31;
    const int wid  = tid >> 5;
    const int wm   = wid >> 2;
    const int wn   = wid & 3;

    __shared__ __half sqh[64 * 64];
    __shared__ __half sql[64 * 64];
    __shared__ __half skh[128 * 64];
    __shared__ int    msk[128];
    __shared__ float  redm[64][5];

    const uint32_t bqh = smem_u32(sqh);
    const uint32_t bql = smem_u32(sql);
    const uint32_t bkh = smem_u32(skh);

#pragma unroll
    for (int c = 0; c < 2; c++) {
        int id = tid + c * 256;
        int r = id >> 3, c16 = id & 7;
        uint32_t off = SW128((uint32_t)(r * 128 + c16 * 16));
        CP_ASYNC16(bqh + off, (const void*)&g_qh16[(size_t)(b * M_ + r) * INNER_ + h * DH_ + c16 * 8]);
        CP_ASYNC16(bql + off, (const void*)&g_ql16[(size_t)(b * M_ + r) * INNER_ + h * DH_ + c16 * 8]);
    }
#pragma unroll
    for (int c = 0; c < 4; c++) {
        int id = tid + c * 256;
        int r = id >> 3, c16 = id & 7;
        uint32_t off = SW128((uint32_t)(r * 128 + c16 * 16));
        CP_ASYNC16(bkh + off, (const void*)&g_k16[((size_t)b * N_ + n0 + r) * INNER_ + h * DH_ + c16 * 8]);
    }
    CP_COMMIT;
    if (tid < 128) msk[tid] = mask[b * N_ + n0 + tid];
    CP_WAIT0;
    __syncthreads();

    float acc[2][4][4];
#pragma unroll
    for (int mt = 0; mt < 2; mt++)
#pragma unroll
        for (int nt = 0; nt < 4; nt++)
#pragma unroll
            for (int e = 0; e < 4; e++) acc[mt][nt][e] = 0.f;

#pragma unroll
    for (int ks = 0; ks < 4; ks++) {
        uint32_t ah[2][4], al[2][4], bf[4][2];
#pragma unroll
        for (int mt = 0; mt < 2; mt++) {
            uint32_t r_ = wm * 32 + mt * 16 + (lane & 15);
            uint32_t off = SW128(r_ * 128 + ks * 32 + (lane >> 4) * 16);
            LDMX4(ah[mt], bqh + off);
            LDMX4(al[mt], bql + off);
        }
#pragma unroll
        for (int nt = 0; nt < 4; nt++) {
            uint32_t n_ = wn * 32 + nt * 8 + (lane >> 2);
            bf[nt][0] = lds32(bkh + SW128(n_ * 128 + ks * 32 + (lane & 3) * 4));
            bf[nt][1] = lds32(bkh + SW128(n_ * 128 + ks * 32 + 16 + (lane & 3) * 4));
        }
#pragma unroll
        for (int mt = 0; mt < 2; mt++)
#pragma unroll
            for (int nt = 0; nt < 4; nt++) {
                MMA_F16(acc[mt][nt], ah[mt], bf[nt]);
                MMA_F16(acc[mt][nt], al[mt], bf[nt]);
            }
    }

#pragma unroll
    for (int mt = 0; mt < 2; mt++) {
        int r = wm * 32 + mt * 16 + (lane >> 2);
        float m0 = -FLT_MAX, m1 = -FLT_MAX;
#pragma unroll
        for (int nt = 0; nt < 4; nt++) {
            int c = wn * 32 + nt * 8 + (lane & 3) * 2;
            float v0 = msk[c]     ? -FLT_MAX : acc[mt][nt][0];
            float v1 = msk[c + 1] ? -FLT_MAX : acc[mt][nt][1];
            float v2 = msk[c]     ? -FLT_MAX : acc[mt][nt][2];
            float v3 = msk[c + 1] ? -FLT_MAX : acc[mt][nt][3];
            *reinterpret_cast<float2*>(&g_sim[((size_t)bh * M_ + r) * N_ + n0 + c]) = make_float2(v0, v1);
            *reinterpret_cast<float2*>(&g_sim[((size_t)bh * M_ + r + 8) * N_ + n0 + c]) = make_float2(v2, v3);
            m0 = fmaxf(m0, fmaxf(v0, v1));
            m1 = fmaxf(m1, fmaxf(v2, v3));
        }
#pragma unroll
        for (int s = 1; s < 4; s <<= 1) {
            m0 = fmaxf(m0, __shfl_xor_sync(0xffffffffu, m0, s));
            m1 = fmaxf(m1, __shfl_xor_sync(0xffffffffu, m1, s));
        }
        if ((lane & 3) == 0) {
            redm[r][wn]     = m0;
            redm[r + 8][wn] = m1;
        }
    }
    __syncthreads();
    if (tid < 64) {
        float m = fmaxf(fmaxf(redm[tid][0], redm[tid][1]), fmaxf(redm[tid][2], redm[tid][3]));
        atomicMax(&g_rmax_ord[bh * M_ + tid], f2o(m));
    }
}

// ==================== pv via mma ==========================================
#define PVROW 72
__global__ __launch_bounds__(256) void pv_mma_kernel(const int* __restrict__ mask)
{
    const int ch = blockIdx.x;
    const int bh = blockIdx.y;
    const int b  = bh >> 4;
    const int h  = bh & 15;
    const int tid = threadIdx.x;
    const int lane = tid & 31;
    const int wid  = tid >> 5;
    const int wm   = wid >> 2;
    const int wn   = wid & 3;

    __shared__ __half ph[64 * PVROW];
    __shared__ __half pl[64 * PVROW];
    __shared__ __half vh[64 * PVROW];
    __shared__ __half vl[64 * PVROW];
    __shared__ float  rs[64];
    __shared__ float  colred[2][4][64];
    __shared__ float  lred[64];

    const uint32_t bph = smem_u32(ph);
    const uint32_t bpl = smem_u32(pl);
    const uint32_t bvh = smem_u32(vh);
    const uint32_t bvl = smem_u32(vl);

    if (tid < 64) rs[tid] = o2f(g_rmax_ord[bh * M_ + tid]);
    __syncthreads();

    const int cq = tid >> 6;
    const int ccol = tid & 63;

    float acc[2][2][4];
#pragma unroll
    for (int mt = 0; mt < 2; mt++)
#pragma unroll
        for (int nt = 0; nt < 2; nt++)
#pragma unroll
            for (int e = 0; e < 4; e++) acc[mt][nt][e] = 0.f;
    float lossloc = 0.f, denloc = 0.f;

    const int jt0 = ch * (64 / NCH_);
    for (int jt = jt0; jt < jt0 + 64 / NCH_; jt++) {
        const int j0 = jt * 64;

#pragma unroll
        for (int c = 0; c < 2; c++) {
            int id = tid + c * 256;
            int r = id >> 3, c16 = id & 7;
            uint32_t doff = (uint32_t)(r * (PVROW * 2) + c16 * 16);
            size_t gsrc = ((size_t)b * N_ + j0 + r) * INNER_ + h * DH_ + c16 * 8;
            CP_ASYNC16(bvh + doff, (const void*)&g_vh16[gsrc]);
            CP_ASYNC16(bvl + doff, (const void*)&g_vl16[gsrc]);
        }
        CP_COMMIT;

        float st = 0.f, st2 = 0.f;
#pragma unroll 4
        for (int k = 0; k < 16; k++) {
            int r = cq + 4 * k;
            float sv = g_sim[((size_t)bh * M_ + r) * N_ + j0 + ccol];
            float t = sv - rs[r];
            float e = __expf(t);
            __half hp = __float2half_rn(e);
            __half lp = __float2half_rn(e - __half2float(hp));
            ph[r * PVROW + ccol] = hp;
            pl[r * PVROW + ccol] = lp;
            st += t; st2 += t * t;
        }
        colred[0][cq][ccol] = st;
        colred[1][cq][ccol] = st2;
        CP_WAIT0;
        __syncthreads();

        if (tid < 64) {
            if (mask[b * N_ + j0 + tid] == 0) {
                float s  = colred[0][0][tid] + colred[0][1][tid] + colred[0][2][tid] + colred[0][3][tid];
                float ss = colred[1][0][tid] + colred[1][1][tid] + colred[1][2][tid] + colred[1][3][tid];
                float var = (ss - s * s * (1.0f / 64.f)) * (1.0f / 63.f);
                float sd  = sqrtf(var + 1e-4f);
                lossloc += fmaxf(1.0f - sd, 0.0f);
            }
            float sde = 0.f;
            const __half2* rh = reinterpret_cast<const __half2*>(&ph[tid * PVROW]);
            const __half2* rl = reinterpret_cast<const __half2*>(&pl[tid * PVROW]);
#pragma unroll 8
            for (int j2 = 0; j2 < 32; j2++) {
                float2 a = __half22float2(rh[j2]);
                float2 c2 = __half22float2(rl[j2]);
                sde += a.x + a.y + c2.x + c2.y;
            }
            denloc += sde;
        }

#pragma unroll
        for (int ks = 0; ks < 4; ks++) {
            uint32_t aph[2][4], apl[2][4], bh2[2][2], bl2[2][2];
#pragma unroll
            for (int mt = 0; mt < 2; mt++) {
                uint32_t r_ = wm * 32 + mt * 16 + (lane & 15);
                uint32_t off = r_ * (PVROW * 2) + ks * 32 + (lane >> 4) * 16;
                LDMX4(aph[mt], bph + off);
                LDMX4(apl[mt], bpl + off);
            }
#pragma unroll
            for (int nt = 0; nt < 2; nt++) {
                uint32_t jr = (uint32_t)(ks * 16 + (lane & 15));
                uint32_t off = jr * (PVROW * 2) + (wn * 16 + nt * 8) * 2;
                LDMX2T(bh2[nt], bvh + off);
                LDMX2T(bl2[nt], bvl + off);
            }
#pragma unroll
            for (int mt = 0; mt < 2; mt++)
#pragma unroll
                for (int nt = 0; nt < 2; nt++) {
                    MMA_F16(acc[mt][nt], aph[mt], bh2[nt]);
                    MMA_F16(acc[mt][nt], aph[mt], bl2[nt]);
                    MMA_F16(acc[mt][nt], apl[mt], bh2[nt]);
                }
        }
        __syncthreads();
    }

    float* pvb = &g_pvpart[((size_t)bh * NCH_ + ch) * M_ * DH_];
#pragma unroll
    for (int mt = 0; mt < 2; mt++) {
        int i = wm * 32 + mt * 16 + (lane >> 2);
#pragma unroll
        for (int nt = 0; nt < 2; nt++) {
            int d = wn * 16 + nt * 8 + (lane & 3) * 2;
            *reinterpret_cast<float2*>(&pvb[i * DH_ + d]) = make_float2(acc[mt][nt][0], acc[mt][nt][1]);
            *reinterpret_cast<float2*>(&pvb[(i + 8) * DH_ + d]) = make_float2(acc[mt][nt][2], acc[mt][nt][3]);
        }
    }
    if (tid < 64) g_denpart[(bh * NCH_ + ch) * M_ + tid] = denloc;

    if (tid < 64) lred[tid] = lossloc;
    __syncthreads();
    if (tid < 32) lred[tid] += lred[tid + 32];
    __syncthreads();
    if (tid == 0) {
        float s = 0.f;
#pragma unroll
        for (int t = 0; t < 32; t++) s += lred[t];
        g_losschunk[bh * NCH_ + ch] = s;
    }
}

// ==================== pv combine -> attn fp16 hi/lo =======================
__global__ __launch_bounds__(256) void pv_combine_kernel()
{
    const int bh = blockIdx.x;
    const int b  = bh >> 4;
    const int h  = bh & 15;
    const int tid = threadIdx.x;

    __shared__ float dinv[64];
    if (tid < 64) {
        float d = 0.f;
#pragma unroll
        for (int c = 0; c < NCH_; c++) d += g_denpart[(bh * NCH_ + c) * M_ + tid];
        dinv[tid] = 1.0f / d;
    }
    if (tid == 64) {
        float s = 0.f;
#pragma unroll
        for (int c = 0; c < NCH_; c++) s += g_losschunk[bh * NCH_ + c];
        g_losspart[bh] = s;
    }
    __syncthreads();

    const float* pvb = &g_pvpart[(size_t)bh * NCH_ * M_ * DH_];
    for (int idx = tid; idx < M_ * DH_; idx += 256) {
        int i = idx >> 6, d = idx & 63;
        float s = 0.f;
#pragma unroll
        for (int c = 0; c < NCH_; c++) s += pvb[c * M_ * DH_ + idx];
        float val = s * dinv[i];
        __half hp = __float2half_rn(val);
        __half lp = __float2half_rn(val - __half2float(hp));
        size_t gi = ((size_t)b * M_ + i) * INNER_ + h * DH_ + d;
        g_ah[gi] = hp;
        g_al[gi] = lp;
    }
}

__global__ __launch_bounds__(128) void loss_final_kernel(float* __restrict__ out, int idx)
{
    __shared__ float red[128];
    red[threadIdx.x] = g_losspart[threadIdx.x];
    __syncthreads();
    for (int t = 64; t > 0; t >>= 1) {
        if (threadIdx.x < t) red[threadIdx.x] += red[threadIdx.x + t];
        __syncthreads();
    }
    if (threadIdx.x == 0) out[idx] = red[0] * (1.0f / (float)(B_ * H_ * N_));
}

// ==================== launch ==============================================
extern "C" void kernel_launch(void* const* d_in, const int* in_sizes, int n_in,
                              void* d_out, int out_size)
{
    const float* x       = (const float*)d_in[0];
    const float* latents = (const float*)d_in[1];
    const int*   mask    = (const int*)d_in[2];
    const float* Wq      = (const float*)d_in[3];
    const float* Wkv     = (const float*)d_in[4];
    const float* Wout    = (const float*)d_in[5];
    float*       out     = (float*)d_out;

    cudaFuncSetAttribute(gemm16_kernel, cudaFuncAttributeMaxDynamicSharedMemorySize, GSMEM3);

    void *pxh, *pkvh, *pqh, *poh, *plh, *pll, *pah, *pal;
    void *pq, *pvh, *pvl, *pk16, *pqh16, *pql16;
    cudaGetSymbolAddress(&pxh, g_xh);
    cudaGetSymbolAddress(&pkvh, g_wkvh);
    cudaGetSymbolAddress(&pqh, g_wqh);  cudaGetSymbolAddress(&poh, g_wouth);
    cudaGetSymbolAddress(&plh, g_lath); cudaGetSymbolAddress(&pll, g_latl);
    cudaGetSymbolAddress(&pah, g_ah);   cudaGetSymbolAddress(&pal, g_al);
    cudaGetSymbolAddress(&pq, g_q);
    cudaGetSymbolAddress(&pvh, g_vh16); cudaGetSymbolAddress(&pvl, g_vl16);
    cudaGetSymbolAddress(&pk16, g_k16);
    cudaGetSymbolAddress(&pqh16, g_qh16);
    cudaGetSymbolAddress(&pql16, g_ql16);

    const __half* wk_h = (const __half*)pkvh;
    const __half* wv_h = (const __half*)pkvh + (size_t)INNER_ * DIM_;

    // L1: x -> fp16 hi only (lo unused now)
    split2_kernel<<<(B_ * N_ * DIM_ / 4 + 255) / 256, 256>>>(
        x, (__half*)pxh, nullptr, B_ * N_ * DIM_ / 4);

    // L2: split weights + latents, init rmax/loss
    prep_kernel<<<(PR_END + 255) / 256, 256>>>(Wkv, Wq, Wout, latents);

    // L3: q = latents @ Wq^T * scale  (2-pass fp32)
    gemm16_kernel<<<dim3(INNER_ / 256, (B_ * M_) / 128), 512, GSMEM3>>>(
        (const __half*)plh, (const __half*)pll, (const __half*)pqh,
        (float*)pq, nullptr, nullptr, INNER_, DIM_, 0.125f);

    // L4: k16 = x_h @ Wk^T  (1-pass, fp16)   (profiled launch)
    gemm16_kernel<<<dim3(INNER_ / 256, (B_ * N_) / 128), 512, GSMEM3>>>(
        (const __half*)pxh, nullptr, wk_h,
        nullptr, (__half*)pk16, nullptr, INNER_, DIM_, 1.0f);

    // L5: v = x_h @ Wv^T  (1-pass, fp16 hi/lo output)
    gemm16_kernel<<<dim3(INNER_ / 256, (B_ * N_) / 128), 512, GSMEM3>>>(
        (const __half*)pxh, nullptr, wv_h,
        nullptr, (__half*)pvh, (__half*)pvl, INNER_, DIM_, 1.0f);

    // L6: split q -> fp16 hi/lo for sim
    split2_kernel<<<(B_ * M_ * INNER_ / 4 + 255) / 256, 256>>>(
        (const float*)pq, (__half*)pqh16, (__half*)pql16, B_ * M_ * INNER_ / 4);

    // L7: sim via tensor cores
    sim_mma_kernel<<<dim3(N_ / 128, B_ * H_), 256>>>(mask);

    // L8: pv via tensor cores
    pv_mma_kernel<<<dim3(NCH_, B_ * H_), 256>>>(mask);

    // L9: combine -> attn fp16 hi/lo
    pv_combine_kernel<<<B_ * H_, 256>>>();

    // L10: loss finalize
    loss_final_kernel<<<1, 128>>>(out, out_size - 1);

    // L11: out = attn_out @ Wout^T  (2-pass fp32)
    gemm16_kernel<<<dim3(DIM_ / 256, (B_ * M_) / 128), 512, GSMEM3>>>(
        (const __half*)pah, (const __half*)pal, (const __half*)poh,
        out, nullptr, nullptr, DIM_, INNER_, 1.0f);
}

// round 15
// speedup vs baseline: 1.1083x; 1.0833x over previous
#include <cuda_runtime.h>
#include <cuda_fp16.h>
#include <cfloat>
#include <math.h>
#include <cstdint>

#define B_   8
#define N_   4096
#define M_   64
#define DIM_ 1024
#define H_   16
#define DH_  64
#define INNER_ 1024
#define KV2_  2048
#define NCH_  4

// ==================== scratch =============================================
__device__ __half   g_k16[(size_t)B_ * N_ * INNER_];
__device__ __half   g_vh16[(size_t)B_ * N_ * INNER_];
__device__ __half   g_vl16[(size_t)B_ * N_ * INNER_];
__device__ float    g_sim[(size_t)B_ * H_ * M_ * N_];
__device__ unsigned g_rmax_ord[B_ * H_ * M_];
__device__ float    g_losspart[B_ * H_];
__device__ float    g_pvpart[B_ * H_ * NCH_ * M_ * DH_];
__device__ float    g_denpart[B_ * H_ * NCH_ * M_];
__device__ float    g_losschunk[B_ * H_ * NCH_];

// fp16 split buffers
__device__ __half g_xh[(size_t)B_ * N_ * DIM_];
__device__ __half g_wkvh[KV2_ * DIM_];
__device__ __half g_wqh[INNER_ * DIM_];
__device__ __half g_wouth[DIM_ * INNER_];
__device__ __half g_lath[B_ * M_ * DIM_];
__device__ __half g_latl[B_ * M_ * DIM_];
__device__ __half g_ah[B_ * M_ * INNER_];
__device__ __half g_al[B_ * M_ * INNER_];
__device__ __half g_qh16[B_ * M_ * INNER_];
__device__ __half g_ql16[B_ * M_ * INNER_];

// ==================== helpers =============================================
__device__ __forceinline__ uint32_t smem_u32(const void* p) {
    uint32_t a;
    asm("{ .reg .u64 t; cvta.to.shared.u64 t, %1; cvt.u32.u64 %0, t; }" : "=r"(a) : "l"(p));
    return a;
}
__device__ __forceinline__ uint32_t lds32(uint32_t a) {
    uint32_t v;
    asm volatile("ld.shared.b32 %0, [%1];" : "=r"(v) : "r"(a));
    return v;
}
#define LDMX4(r, addr) \
    asm volatile("ldmatrix.sync.aligned.m8n8.x4.shared.b16 {%0,%1,%2,%3}, [%4];" \
        : "=r"((r)[0]), "=r"((r)[1]), "=r"((r)[2]), "=r"((r)[3]) : "r"(addr))
#define LDMX2T(r, addr) \
    asm volatile("ldmatrix.sync.aligned.m8n8.x2.trans.shared.b16 {%0,%1}, [%2];" \
        : "=r"((r)[0]), "=r"((r)[1]) : "r"(addr))
#define MMA_F16(c, a, b) \
    asm volatile("mma.sync.aligned.m16n8k16.row.col.f32.f16.f16.f32 " \
        "{%0,%1,%2,%3}, {%4,%5,%6,%7}, {%8,%9}, {%0,%1,%2,%3};" \
        : "+f"((c)[0]), "+f"((c)[1]), "+f"((c)[2]), "+f"((c)[3]) \
        : "r"((a)[0]), "r"((a)[1]), "r"((a)[2]), "r"((a)[3]), "r"((b)[0]), "r"((b)[1]))
#define CP_ASYNC16(dst, src) \
    asm volatile("cp.async.cg.shared.global [%0], [%1], 16;" :: "r"(dst), "l"(src) : "memory")
#define CP_COMMIT asm volatile("cp.async.commit_group;" ::: "memory")
#define CP_WAIT1  asm volatile("cp.async.wait_group 1;" ::: "memory")
#define CP_WAIT0  asm volatile("cp.async.wait_group 0;" ::: "memory")
#define SW128(off) ((off) ^ (((off) >> 3) & 0x70))

__device__ __forceinline__ uint2 hi_pack_h(float4 v) {
    __half2 p0(__float2half_rn(v.x), __float2half_rn(v.y));
    __half2 p1(__float2half_rn(v.z), __float2half_rn(v.w));
    uint2 r;
    r.x = *reinterpret_cast<uint32_t*>(&p0);
    r.y = *reinterpret_cast<uint32_t*>(&p1);
    return r;
}
__device__ __forceinline__ uint2 lo_pack_h(float4 v) {
    float4 l;
    l.x = v.x - __half2float(__float2half_rn(v.x));
    l.y = v.y - __half2float(__float2half_rn(v.y));
    l.z = v.z - __half2float(__float2half_rn(v.z));
    l.w = v.w - __half2float(__float2half_rn(v.w));
    return hi_pack_h(l);
}
__device__ __forceinline__ unsigned f2o(float f) {
    unsigned b = __float_as_uint(f);
    return (b & 0x80000000u) ? ~b : (b | 0x80000000u);
}
__device__ __forceinline__ float o2f(unsigned u) {
    return __uint_as_float((u & 0x80000000u) ? (u ^ 0x80000000u) : ~u);
}

// ==================== split kernels =======================================
__global__ __launch_bounds__(256) void split2_kernel(
    const float* __restrict__ src, __half* __restrict__ h, __half* __restrict__ l, int n4)
{
    int i = blockIdx.x * 256 + threadIdx.x;
    if (i >= n4) return;
    float4 v = reinterpret_cast<const float4*>(src)[i];
    reinterpret_cast<uint2*>(h)[i] = hi_pack_h(v);
    if (l) reinterpret_cast<uint2*>(l)[i] = lo_pack_h(v);
}

#define PR_WKV  524288
#define PR_WQ   (PR_WKV + 262144)
#define PR_WOUT (PR_WQ + 262144)
#define PR_LAT  (PR_WOUT + 131072)
#define PR_RM   (PR_LAT + 1024)
#define PR_END  (PR_RM + 128)
__global__ __launch_bounds__(256) void prep_kernel(
    const float* __restrict__ Wkv, const float* __restrict__ Wq,
    const float* __restrict__ Wout, const float* __restrict__ latents)
{
    int id = blockIdx.x * 256 + threadIdx.x;
    if (id < PR_WKV) {
        float4 v = reinterpret_cast<const float4*>(Wkv)[id];
        reinterpret_cast<uint2*>(g_wkvh)[id] = hi_pack_h(v);
    } else if (id < PR_WQ) {
        int i = id - PR_WKV;
        float4 v = reinterpret_cast<const float4*>(Wq)[i];
        reinterpret_cast<uint2*>(g_wqh)[i] = hi_pack_h(v);
    } else if (id < PR_WOUT) {
        int i = id - PR_WQ;
        float4 v = reinterpret_cast<const float4*>(Wout)[i];
        reinterpret_cast<uint2*>(g_wouth)[i] = hi_pack_h(v);
    } else if (id < PR_LAT) {
        int i = id - PR_WOUT;
        float4 v = reinterpret_cast<const float4*>(latents)[i];
        reinterpret_cast<uint2*>(g_lath)[i] = hi_pack_h(v);
        reinterpret_cast<uint2*>(g_latl)[i] = lo_pack_h(v);
    } else if (id < PR_RM) {
        g_rmax_ord[id - PR_LAT] = 0u;
    } else if (id < PR_END) {
        g_losspart[id - PR_RM] = 0.f;
    }
}

// ==================== fp16 GEMM: 128x256 tile, 512 thr, 3-stage ===========
#define A_TILE3    16384
#define B_OFF3     32768
#define STAGE3     65536
#define GSMEM3     196608

__global__ __launch_bounds__(512, 1) void gemm16_kernel(
    const __half* __restrict__ Ah, const __half* __restrict__ Al,
    const __half* __restrict__ Bh, float* __restrict__ C,
    __half* __restrict__ Ch, __half* __restrict__ Chl,
    int Ng, int Kg, float alpha)
{
    extern __shared__ char sm[];
    const uint32_t smb = smem_u32(sm);
    const int tid  = threadIdx.x;
    const int lane = tid & 31;
    const int wid  = tid >> 5;
    const int wm   = wid >> 3;
    const int wn   = wid & 7;
    const int row0 = blockIdx.y * 128;
    const int col0 = blockIdx.x * 256;
    const bool two_pass = (Al != nullptr);

    float acc[4][4][4];
#pragma unroll
    for (int mt = 0; mt < 4; mt++)
#pragma unroll
        for (int nt = 0; nt < 4; nt++)
#pragma unroll
            for (int e = 0; e < 4; e++) acc[mt][nt][e] = 0.f;

#define LOAD(i) do { \
    const int s_ = (i) % 3; \
    const uint32_t sb_ = smb + s_ * STAGE3; \
    const int k0_ = (i) * 64; \
    _Pragma("unroll") \
    for (int c_ = 0; c_ < 2; c_++) { \
        int id_ = tid + c_ * 512; \
        int r_ = id_ >> 3, c16_ = id_ & 7; \
        uint32_t doff_ = SW128((uint32_t)(r_ * 128 + c16_ * 16)); \
        CP_ASYNC16(sb_ + doff_,              (const void*)&Ah[(size_t)(row0 + r_) * Kg + k0_ + c16_ * 8]); \
        if (two_pass) \
            CP_ASYNC16(sb_ + A_TILE3 + doff_, (const void*)&Al[(size_t)(row0 + r_) * Kg + k0_ + c16_ * 8]); \
    } \
    _Pragma("unroll") \
    for (int c_ = 0; c_ < 4; c_++) { \
        int id_ = tid + c_ * 512; \
        int r_ = id_ >> 3, c16_ = id_ & 7; \
        uint32_t doff_ = SW128((uint32_t)(r_ * 128 + c16_ * 16)); \
        CP_ASYNC16(sb_ + B_OFF3 + doff_, (const void*)&Bh[(size_t)(col0 + r_) * Kg + k0_ + c16_ * 8]); \
    } } while (0)

#define COMPUTE(s) do { \
    const uint32_t sb_ = smb + (s) * STAGE3; \
    _Pragma("unroll") \
    for (int ks = 0; ks < 4; ks++) { \
        uint32_t ah[4][4], al[4][4], bh[4][2]; \
        _Pragma("unroll") \
        for (int mt = 0; mt < 4; mt++) { \
            uint32_t r_ = wm * 64 + mt * 16 + (lane & 15); \
            uint32_t off_ = SW128(r_ * 128 + ks * 32 + (lane >> 4) * 16); \
            LDMX4(ah[mt], sb_ + off_); \
            if (two_pass) LDMX4(al[mt], sb_ + A_TILE3 + off_); \
        } \
        _Pragma("unroll") \
        for (int nt = 0; nt < 4; nt++) { \
            uint32_t n_ = wn * 32 + nt * 8 + (lane >> 2); \
            bh[nt][0] = lds32(sb_ + B_OFF3 + SW128(n_ * 128 + ks * 32 + (lane & 3) * 4)); \
            bh[nt][1] = lds32(sb_ + B_OFF3 + SW128(n_ * 128 + ks * 32 + 16 + (lane & 3) * 4)); \
        } \
        _Pragma("unroll") \
        for (int mt = 0; mt < 4; mt++) \
        _Pragma("unroll") \
        for (int nt = 0; nt < 4; nt++) { \
            MMA_F16(acc[mt][nt], ah[mt], bh[nt]); \
            if (two_pass) MMA_F16(acc[mt][nt], al[mt], bh[nt]); \
        } \
    } } while (0)

    const int nk = Kg >> 6;
    LOAD(0); CP_COMMIT;
    LOAD(1); CP_COMMIT;
    for (int i = 0; i < nk; i++) {
        if (i + 1 < nk) { CP_WAIT1; } else { CP_WAIT0; }
        __syncthreads();
        if (i + 2 < nk) { LOAD(i + 2); CP_COMMIT; }
        COMPUTE(i % 3);
    }

#pragma unroll
    for (int mt = 0; mt < 4; mt++) {
        int r = row0 + wm * 64 + mt * 16 + (lane >> 2);
#pragma unroll
        for (int nt = 0; nt < 4; nt++) {
            int c = col0 + wn * 32 + nt * 8 + (lane & 3) * 2;
            float2 v0 = make_float2(alpha * acc[mt][nt][0], alpha * acc[mt][nt][1]);
            float2 v1 = make_float2(alpha * acc[mt][nt][2], alpha * acc[mt][nt][3]);
            if (C) {
                *reinterpret_cast<float2*>(&C[(size_t)r * Ng + c]) = v0;
                *reinterpret_cast<float2*>(&C[(size_t)(r + 8) * Ng + c]) = v1;
            }
            if (Ch) {
                __half h00 = __float2half_rn(v0.x), h01 = __float2half_rn(v0.y);
                __half h10 = __float2half_rn(v1.x), h11 = __float2half_rn(v1.y);
                *reinterpret_cast<__half2*>(&Ch[(size_t)r * Ng + c]) = __half2(h00, h01);
                *reinterpret_cast<__half2*>(&Ch[(size_t)(r + 8) * Ng + c]) = __half2(h10, h11);
                if (Chl) {
                    __half2 l0(__float2half_rn(v0.x - __half2float(h00)),
                               __float2half_rn(v0.y - __half2float(h01)));
                    __half2 l1(__float2half_rn(v1.x - __half2float(h10)),
                               __float2half_rn(v1.y - __half2float(h11)));
                    *reinterpret_cast<__half2*>(&Chl[(size_t)r * Ng + c]) = l0;
                    *reinterpret_cast<__half2*>(&Chl[(size_t)(r + 8) * Ng + c]) = l1;
                }
            }
        }
    }
#undef LOAD
#undef COMPUTE
}

// ==================== sim via mma.sync + mask + rowmax ====================
__global__ __launch_bounds__(256) void sim_mma_kernel(const int* __restrict__ mask)
{
    const int bh = blockIdx.y;
    const int b  = bh >> 4;
    const int h  = bh & 15;
    const int n0 = blockIdx.x * 128;
    const int tid = threadIdx.x;
    const int lane = tid & 31;
    const int wid  = tid >> 5;
    const int wm   = wid >> 2;
    const int wn   = wid & 3;

    __shared__ __half sqh[64 * 64];
    __shared__ __half sql[64 * 64];
    __shared__ __half skh[128 * 64];
    __shared__ int    msk[128];
    __shared__ float  redm[64][5];

    const uint32_t bqh = smem_u32(sqh);
    const uint32_t bql = smem_u32(sql);
    const uint32_t bkh = smem_u32(skh);

#pragma unroll
    for (int c = 0; c < 2; c++) {
        int id = tid + c * 256;
        int r = id >> 3, c16 = id & 7;
        uint32_t off = SW128((uint32_t)(r * 128 + c16 * 16));
        CP_ASYNC16(bqh + off, (const void*)&g_qh16[(size_t)(b * M_ + r) * INNER_ + h * DH_ + c16 * 8]);
        CP_ASYNC16(bql + off, (const void*)&g_ql16[(size_t)(b * M_ + r) * INNER_ + h * DH_ + c16 * 8]);
    }
#pragma unroll
    for (int c = 0; c < 4; c++) {
        int id = tid + c * 256;
        int r = id >> 3, c16 = id & 7;
        uint32_t off = SW128((uint32_t)(r * 128 + c16 * 16));
        CP_ASYNC16(bkh + off, (const void*)&g_k16[((size_t)b * N_ + n0 + r) * INNER_ + h * DH_ + c16 * 8]);
    }
    CP_COMMIT;
    if (tid < 128) msk[tid] = mask[b * N_ + n0 + tid];
    CP_WAIT0;
    __syncthreads();

    float acc[2][4][4];
#pragma unroll
    for (int mt = 0; mt < 2; mt++)
#pragma unroll
        for (int nt = 0; nt < 4; nt++)
#pragma unroll
            for (int e = 0; e < 4; e++) acc[mt][nt][e] = 0.f;

#pragma unroll
    for (int ks = 0; ks < 4; ks++) {
        uint32_t ah[2][4], al[2][4], bf[4][2];
#pragma unroll
        for (int mt = 0; mt < 2; mt++) {
            uint32_t r_ = wm * 32 + mt * 16 + (lane & 15);
            uint32_t off = SW128(r_ * 128 + ks * 32 + (lane >> 4) * 16);
            LDMX4(ah[mt], bqh + off);
            LDMX4(al[mt], bql + off);
        }
#pragma unroll
        for (int nt = 0; nt < 4; nt++) {
            uint32_t n_ = wn * 32 + nt * 8 + (lane >> 2);
            bf[nt][0] = lds32(bkh + SW128(n_ * 128 + ks * 32 + (lane & 3) * 4));
            bf[nt][1] = lds32(bkh + SW128(n_ * 128 + ks * 32 + 16 + (lane & 3) * 4));
        }
#pragma unroll
        for (int mt = 0; mt < 2; mt++)
#pragma unroll
            for (int nt = 0; nt < 4; nt++) {
                MMA_F16(acc[mt][nt], ah[mt], bf[nt]);
                MMA_F16(acc[mt][nt], al[mt], bf[nt]);
            }
    }

#pragma unroll
    for (int mt = 0; mt < 2; mt++) {
        int r = wm * 32 + mt * 16 + (lane >> 2);
        float m0 = -FLT_MAX, m1 = -FLT_MAX;
#pragma unroll
        for (int nt = 0; nt < 4; nt++) {
            int c = wn * 32 + nt * 8 + (lane & 3) * 2;
            float v0 = msk[c]     ? -FLT_MAX : acc[mt][nt][0];
            float v1 = msk[c + 1] ? -FLT_MAX : acc[mt][nt][1];
            float v2 = msk[c]     ? -FLT_MAX : acc[mt][nt][2];
            float v3 = msk[c + 1] ? -FLT_MAX : acc[mt][nt][3];
            *reinterpret_cast<float2*>(&g_sim[((size_t)bh * M_ + r) * N_ + n0 + c]) = make_float2(v0, v1);
            *reinterpret_cast<float2*>(&g_sim[((size_t)bh * M_ + r + 8) * N_ + n0 + c]) = make_float2(v2, v3);
            m0 = fmaxf(m0, fmaxf(v0, v1));
            m1 = fmaxf(m1, fmaxf(v2, v3));
        }
#pragma unroll
        for (int s = 1; s < 4; s <<= 1) {
            m0 = fmaxf(m0, __shfl_xor_sync(0xffffffffu, m0, s));
            m1 = fmaxf(m1, __shfl_xor_sync(0xffffffffu, m1, s));
        }
        if ((lane & 3) == 0) {
            redm[r][wn]     = m0;
            redm[r + 8][wn] = m1;
        }
    }
    __syncthreads();
    if (tid < 64) {
        float m = fmaxf(fmaxf(redm[tid][0], redm[tid][1]), fmaxf(redm[tid][2], redm[tid][3]));
        atomicMax(&g_rmax_ord[bh * M_ + tid], f2o(m));
    }
}

// ==================== pv via mma ==========================================
#define PVROW 72
__global__ __launch_bounds__(256) void pv_mma_kernel(const int* __restrict__ mask)
{
    const int ch = blockIdx.x;
    const int bh = blockIdx.y;
    const int b  = bh >> 4;
    const int h  = bh & 15;
    const int tid = threadIdx.x;
    const int lane = tid & 31;
    const int wid  = tid >> 5;
    const int wm   = wid >> 2;
    const int wn   = wid & 3;

    __shared__ __half ph[64 * PVROW];
    __shared__ __half pl[64 * PVROW];
    __shared__ __half vh[64 * PVROW];
    __shared__ __half vl[64 * PVROW];
    __shared__ float  rs[64];
    __shared__ float  colred[2][4][64];
    __shared__ float  lred[64];

    const uint32_t bph = smem_u32(ph);
    const uint32_t bpl = smem_u32(pl);
    const uint32_t bvh = smem_u32(vh);
    const uint32_t bvl = smem_u32(vl);

    if (tid < 64) rs[tid] = o2f(g_rmax_ord[bh * M_ + tid]);
    __syncthreads();

    const int cq = tid >> 6;
    const int ccol = tid & 63;

    float acc[2][2][4];
#pragma unroll
    for (int mt = 0; mt < 2; mt++)
#pragma unroll
        for (int nt = 0; nt < 2; nt++)
#pragma unroll
            for (int e = 0; e < 4; e++) acc[mt][nt][e] = 0.f;
    float lossloc = 0.f, denloc = 0.f;

    const int jt0 = ch * (64 / NCH_);
    for (int jt = jt0; jt < jt0 + 64 / NCH_; jt++) {
        const int j0 = jt * 64;

#pragma unroll
        for (int c = 0; c < 2; c++) {
            int id = tid + c * 256;
            int r = id >> 3, c16 = id & 7;
            uint32_t doff = (uint32_t)(r * (PVROW * 2) + c16 * 16);
            size_t gsrc = ((size_t)b * N_ + j0 + r) * INNER_ + h * DH_ + c16 * 8;
            CP_ASYNC16(bvh + doff, (const void*)&g_vh16[gsrc]);
            CP_ASYNC16(bvl + doff, (const void*)&g_vl16[gsrc]);
        }
        CP_COMMIT;

        float st = 0.f, st2 = 0.f;
#pragma unroll 4
        for (int k = 0; k < 16; k++) {
            int r = cq + 4 * k;
            float sv = g_sim[((size_t)bh * M_ + r) * N_ + j0 + ccol];
            float t = sv - rs[r];
            float e = __expf(t);
            __half hp = __float2half_rn(e);
            __half lp = __float2half_rn(e - __half2float(hp));
            ph[r * PVROW + ccol] = hp;
            pl[r * PVROW + ccol] = lp;
            st += t; st2 += t * t;
        }
        colred[0][cq][ccol] = st;
        colred[1][cq][ccol] = st2;
        CP_WAIT0;
        __syncthreads();

        if (tid < 64) {
            if (mask[b * N_ + j0 + tid] == 0) {
                float s  = colred[0][0][tid] + colred[0][1][tid] + colred[0][2][tid] + colred[0][3][tid];
                float ss = colred[1][0][tid] + colred[1][1][tid] + colred[1][2][tid] + colred[1][3][tid];
                float var = (ss - s * s * (1.0f / 64.f)) * (1.0f / 63.f);
                float sd  = sqrtf(var + 1e-4f);
                lossloc += fmaxf(1.0f - sd, 0.0f);
            }
            float sde = 0.f;
            const __half2* rh = reinterpret_cast<const __half2*>(&ph[tid * PVROW]);
            const __half2* rl = reinterpret_cast<const __half2*>(&pl[tid * PVROW]);
#pragma unroll 8
            for (int j2 = 0; j2 < 32; j2++) {
                float2 a = __half22float2(rh[j2]);
                float2 c2 = __half22float2(rl[j2]);
                sde += a.x + a.y + c2.x + c2.y;
            }
            denloc += sde;
        }

#pragma unroll
        for (int ks = 0; ks < 4; ks++) {
            uint32_t aph[2][4], apl[2][4], bh2[2][2], bl2[2][2];
#pragma unroll
            for (int mt = 0; mt < 2; mt++) {
                uint32_t r_ = wm * 32 + mt * 16 + (lane & 15);
                uint32_t off = r_ * (PVROW * 2) + ks * 32 + (lane >> 4) * 16;
                LDMX4(aph[mt], bph + off);
                LDMX4(apl[mt], bpl + off);
            }
#pragma unroll
            for (int nt = 0; nt < 2; nt++) {
                uint32_t jr = (uint32_t)(ks * 16 + (lane & 15));
                uint32_t off = jr * (PVROW * 2) + (wn * 16 + nt * 8) * 2;
                LDMX2T(bh2[nt], bvh + off);
                LDMX2T(bl2[nt], bvl + off);
            }
#pragma unroll
            for (int mt = 0; mt < 2; mt++)
#pragma unroll
                for (int nt = 0; nt < 2; nt++) {
                    MMA_F16(acc[mt][nt], aph[mt], bh2[nt]);
                    MMA_F16(acc[mt][nt], aph[mt], bl2[nt]);
                    MMA_F16(acc[mt][nt], apl[mt], bh2[nt]);
                }
        }
        __syncthreads();
    }

    float* pvb = &g_pvpart[((size_t)bh * NCH_ + ch) * M_ * DH_];
#pragma unroll
    for (int mt = 0; mt < 2; mt++) {
        int i = wm * 32 + mt * 16 + (lane >> 2);
#pragma unroll
        for (int nt = 0; nt < 2; nt++) {
            int d = wn * 16 + nt * 8 + (lane & 3) * 2;
            *reinterpret_cast<float2*>(&pvb[i * DH_ + d]) = make_float2(acc[mt][nt][0], acc[mt][nt][1]);
            *reinterpret_cast<float2*>(&pvb[(i + 8) * DH_ + d]) = make_float2(acc[mt][nt][2], acc[mt][nt][3]);
        }
    }
    if (tid < 64) g_denpart[(bh * NCH_ + ch) * M_ + tid] = denloc;

    if (tid < 64) lred[tid] = lossloc;
    __syncthreads();
    if (tid < 32) lred[tid] += lred[tid + 32];
    __syncthreads();
    if (tid == 0) {
        float s = 0.f;
#pragma unroll
        for (int t = 0; t < 32; t++) s += lred[t];
        g_losschunk[bh * NCH_ + ch] = s;
    }
}

// ==================== pv combine -> attn fp16 hi/lo =======================
__global__ __launch_bounds__(256) void pv_combine_kernel()
{
    const int bh = blockIdx.x;
    const int b  = bh >> 4;
    const int h  = bh & 15;
    const int tid = threadIdx.x;

    __shared__ float dinv[64];
    if (tid < 64) {
        float d = 0.f;
#pragma unroll
        for (int c = 0; c < NCH_; c++) d += g_denpart[(bh * NCH_ + c) * M_ + tid];
        dinv[tid] = 1.0f / d;
    }
    if (tid == 64) {
        float s = 0.f;
#pragma unroll
        for (int c = 0; c < NCH_; c++) s += g_losschunk[bh * NCH_ + c];
        g_losspart[bh] = s;
    }
    __syncthreads();

    const float* pvb = &g_pvpart[(size_t)bh * NCH_ * M_ * DH_];
    for (int idx = tid; idx < M_ * DH_; idx += 256) {
        int i = idx >> 6, d = idx & 63;
        float s = 0.f;
#pragma unroll
        for (int c = 0; c < NCH_; c++) s += pvb[c * M_ * DH_ + idx];
        float val = s * dinv[i];
        __half hp = __float2half_rn(val);
        __half lp = __float2half_rn(val - __half2float(hp));
        size_t gi = ((size_t)b * M_ + i) * INNER_ + h * DH_ + d;
        g_ah[gi] = hp;
        g_al[gi] = lp;
    }
}

__global__ __launch_bounds__(128) void loss_final_kernel(float* __restrict__ out, int idx)
{
    __shared__ float red[128];
    red[threadIdx.x] = g_losspart[threadIdx.x];
    __syncthreads();
    for (int t = 64; t > 0; t >>= 1) {
        if (threadIdx.x < t) red[threadIdx.x] += red[threadIdx.x + t];
        __syncthreads();
    }
    if (threadIdx.x == 0) out[idx] = red[0] * (1.0f / (float)(B_ * H_ * N_));
}

// ==================== launch ==============================================
extern "C" void kernel_launch(void* const* d_in, const int* in_sizes, int n_in,
                              void* d_out, int out_size)
{
    const float* x       = (const float*)d_in[0];
    const float* latents = (const float*)d_in[1];
    const int*   mask    = (const int*)d_in[2];
    const float* Wq      = (const float*)d_in[3];
    const float* Wkv     = (const float*)d_in[4];
    const float* Wout    = (const float*)d_in[5];
    float*       out     = (float*)d_out;

    cudaFuncSetAttribute(gemm16_kernel, cudaFuncAttributeMaxDynamicSharedMemorySize, GSMEM3);

    // one-time side-stream + events (handles only; no device memory)
    static cudaStream_t s1 = nullptr;
    static cudaEvent_t ev0 = nullptr, evq = nullptr, ev1 = nullptr;
    if (s1 == nullptr) {
        cudaStreamCreateWithFlags(&s1, cudaStreamNonBlocking);
        cudaEventCreateWithFlags(&ev0, cudaEventDisableTiming);
        cudaEventCreateWithFlags(&evq, cudaEventDisableTiming);
        cudaEventCreateWithFlags(&ev1, cudaEventDisableTiming);
    }

    void *pxh, *pkvh, *pqh, *poh, *plh, *pll, *pah, *pal;
    void *pvh, *pvl, *pk16, *pqh16, *pql16;
    cudaGetSymbolAddress(&pxh, g_xh);
    cudaGetSymbolAddress(&pkvh, g_wkvh);
    cudaGetSymbolAddress(&pqh, g_wqh);  cudaGetSymbolAddress(&poh, g_wouth);
    cudaGetSymbolAddress(&plh, g_lath); cudaGetSymbolAddress(&pll, g_latl);
    cudaGetSymbolAddress(&pah, g_ah);   cudaGetSymbolAddress(&pal, g_al);
    cudaGetSymbolAddress(&pvh, g_vh16); cudaGetSymbolAddress(&pvl, g_vl16);
    cudaGetSymbolAddress(&pk16, g_k16);
    cudaGetSymbolAddress(&pqh16, g_qh16);
    cudaGetSymbolAddress(&pql16, g_ql16);

    const __half* wk_h = (const __half*)pkvh;
    const __half* wv_h = (const __half*)pkvh + (size_t)INNER_ * DIM_;

    // s0: split x -> fp16 hi; prep weights/latents
    split2_kernel<<<(B_ * N_ * DIM_ / 4 + 255) / 256, 256>>>(
        x, (__half*)pxh, nullptr, B_ * N_ * DIM_ / 4);
    prep_kernel<<<(PR_END + 255) / 256, 256>>>(Wkv, Wq, Wout, latents);
    cudaEventRecord(ev0, 0);

    // s1 (forked): q-GEMM (2-pass, direct fp16 hi/lo) then v-GEMM (1-pass)
    cudaStreamWaitEvent(s1, ev0, 0);
    gemm16_kernel<<<dim3(INNER_ / 256, (B_ * M_) / 128), 512, GSMEM3, s1>>>(
        (const __half*)plh, (const __half*)pll, (const __half*)pqh,
        nullptr, (__half*)pqh16, (__half*)pql16, INNER_, DIM_, 0.125f);
    cudaEventRecord(evq, s1);
    gemm16_kernel<<<dim3(INNER_ / 256, (B_ * N_) / 128), 512, GSMEM3, s1>>>(
        (const __half*)pxh, nullptr, wv_h,
        nullptr, (__half*)pvh, (__half*)pvl, INNER_, DIM_, 1.0f);
    cudaEventRecord(ev1, s1);

    // s0: k-GEMM (1-pass fp16), concurrent with s1
    gemm16_kernel<<<dim3(INNER_ / 256, (B_ * N_) / 128), 512, GSMEM3>>>(
        (const __half*)pxh, nullptr, wk_h,
        nullptr, (__half*)pk16, nullptr, INNER_, DIM_, 1.0f);

    // s0: sim needs k (s0) + q (evq); overlaps v's tail
    cudaStreamWaitEvent(0, evq, 0);
    sim_mma_kernel<<<dim3(N_ / 128, B_ * H_), 256>>>(mask);

    // s0: pv needs sim + v (ev1)
    cudaStreamWaitEvent(0, ev1, 0);
    pv_mma_kernel<<<dim3(NCH_, B_ * H_), 256>>>(mask);

    pv_combine_kernel<<<B_ * H_, 256>>>();
    loss_final_kernel<<<1, 128>>>(out, out_size - 1);

    gemm16_kernel<<<dim3(DIM_ / 256, (B_ * M_) / 128), 512, GSMEM3>>>(
        (const __half*)pah, (const __half*)pal, (const __half*)poh,
        out, nullptr, nullptr, DIM_, INNER_, 1.0f);
}